// round 7
// baseline (speedup 1.0000x reference)
#include <cuda_runtime.h>
#include <cuda_bf16.h>
#include <cstdint>

#define LVL   32
#define PINS  131072
#define NNETS 1000000
#define TPER  10.0f

// Per-arc validity (bit0 = arc0 valid, bit1 = arc1 valid), computed upfront.
__device__ unsigned char g_valid[(LVL - 1) * PINS];

static __device__ __forceinline__ void atomicMinFloat(float* addr, float val) {
    if (val >= 0.0f) {
        atomicMin((int*)addr, __float_as_int(val));
    } else {
        atomicMax((unsigned int*)addr, __float_as_uint(val));
    }
}

// ---------------- preA (s0): valid bits + arr[0] ----------------
__global__ void sta_preA_kernel(const float* __restrict__ delays,
                                const int2*  __restrict__ net,
                                const unsigned int* __restrict__ mask,
                                float* __restrict__ arr) {
    int i = blockIdx.x * blockDim.x + threadIdx.x;
    if (i < (LVL - 1) * PINS) {
        int2 n = __ldg(&net[i]);
        unsigned v0 = (mask[n.x] == 0u) ? 1u : 0u;
        unsigned v1 = (mask[n.y] == 0u) ? 2u : 0u;
        g_valid[i] = (unsigned char)(v0 | v1);
    }
    if (i < PINS) arr[i] = delays[i];
}

// ---------------- preB (s2): req = TPER + mask re-emit ----------------
__global__ void sta_preB_kernel(const unsigned int* __restrict__ mask,
                                float* __restrict__ req,
                                float* __restrict__ mask_out,
                                long long mask_out_room) {
    int i = blockIdx.x * blockDim.x + threadIdx.x;
    if (i < LVL * PINS) req[i] = TPER;
    if (i < NNETS && i < mask_out_room) mask_out[i] = mask[i] ? 1.0f : 0.0f;
}

// ---------------- fused forward: computes levels l and l+1 from l-1 --------
__global__ void sta_fwd2_kernel(const float* __restrict__ delays,
                                const int2*  __restrict__ src,
                                float* __restrict__ arr,
                                int l) {
    int p = blockIdx.x * blockDim.x + threadIdx.x;
    if (p >= PINS) return;

    const int base0 = (l - 1) * PINS;   // arc rows feeding level l
    const int base1 = l * PINS;         // arc rows feeding level l+1

    // --- everything here depends only on constant inputs (pre-GDS) ---
    int2          s  = __ldg(&src[base0 + p]);
    unsigned char v  = g_valid[base0 + p];
    float         dl = __ldg(&delays[base1 + p]);

    int2          q   = __ldg(&src[base1 + p]);
    unsigned char vq  = g_valid[base1 + p];
    float         dl1 = __ldg(&delays[(l + 1) * PINS + p]);

    int2          sq0 = __ldg(&src[base0 + q.x]);
    int2          sq1 = __ldg(&src[base0 + q.y]);
    unsigned char v0  = g_valid[base0 + q.x];
    unsigned char v1  = g_valid[base0 + q.y];
    float         dq0 = __ldg(&delays[base1 + q.x]);
    float         dq1 = __ldg(&delays[base1 + q.y]);

#if __CUDA_ARCH__ >= 900
    cudaGridDependencySynchronize();
    cudaTriggerProgrammaticLaunchCompletion();
#endif

    const float* ap = arr + base0;
    // 6 independent gathers of the completed level l-1
    float a0 = (v  & 1u) ? __ldg(&ap[s.x])   : 0.0f;
    float a1 = (v  & 2u) ? __ldg(&ap[s.y])   : 0.0f;
    float b0 = (v0 & 1u) ? __ldg(&ap[sq0.x]) : 0.0f;
    float b1 = (v0 & 2u) ? __ldg(&ap[sq0.y]) : 0.0f;
    float c0 = (v1 & 1u) ? __ldg(&ap[sq1.x]) : 0.0f;
    float c1 = (v1 & 2u) ? __ldg(&ap[sq1.y]) : 0.0f;

    // level l, own pin (bitwise identical to single-level computation)
    float ml = dl;
    if (v & 1u) ml = fmaxf(ml, a0 + dl);
    if (v & 2u) ml = fmaxf(ml, a1 + dl);
    arr[base1 + p] = ml;

    // level l recompute for the two sources of level l+1 pin p
    float mq0 = dq0;
    if (v0 & 1u) mq0 = fmaxf(mq0, b0 + dq0);
    if (v0 & 2u) mq0 = fmaxf(mq0, b1 + dq0);
    float mq1 = dq1;
    if (v1 & 1u) mq1 = fmaxf(mq1, c0 + dq1);
    if (v1 & 2u) mq1 = fmaxf(mq1, c1 + dq1);

    // level l+1, own pin
    float m1 = dl1;
    if (vq & 1u) m1 = fmaxf(m1, mq0 + dl1);
    if (vq & 2u) m1 = fmaxf(m1, mq1 + dl1);
    arr[(l + 1) * PINS + p] = m1;
}

// ---------------- single forward level (for the odd last level) ------------
__global__ void sta_fwd1_kernel(const float* __restrict__ delays,
                                const int2*  __restrict__ src,
                                float* __restrict__ arr,
                                int l) {
    int p = blockIdx.x * blockDim.x + threadIdx.x;
    if (p >= PINS) return;

    const int a = (l - 1) * PINS + p;
    int2          s = __ldg(&src[a]);
    unsigned char v = g_valid[a];
    float         d = __ldg(&delays[l * PINS + p]);

#if __CUDA_ARCH__ >= 900
    cudaGridDependencySynchronize();
    cudaTriggerProgrammaticLaunchCompletion();
#endif

    const float* ap = arr + (l - 1) * PINS;
    float a0 = (v & 1u) ? __ldg(&ap[s.x]) : 0.0f;
    float a1 = (v & 2u) ? __ldg(&ap[s.y]) : 0.0f;

    float m = d;
    if (v & 1u) m = fmaxf(m, a0 + d);
    if (v & 2u) m = fmaxf(m, a1 + d);
    arr[l * PINS + p] = m;
}

// ---------------- backward level: scatter-min into req[l] ------------------
__global__ void sta_bwd_kernel(const float* __restrict__ delays,
                               const int2*  __restrict__ src,
                               float* __restrict__ req,
                               int l) {
    int t = blockIdx.x * blockDim.x + threadIdx.x;
    if (t >= PINS / 2) return;

    const int up = (l + 1) * PINS;
    float2 d1 = ((const float2*)(delays + up))[t];
    int4   s  = ((const int4*)(src + l * PINS))[t];
    uchar2 vv = ((const uchar2*)(g_valid + l * PINS))[t];

#if __CUDA_ARCH__ >= 900
    cudaGridDependencySynchronize();
    cudaTriggerProgrammaticLaunchCompletion();
#endif

    float2 r1 = __ldcg((const float2*)(req + up) + t);
    float c0 = r1.x - d1.x;
    float c1 = r1.y - d1.y;

    float* rl = req + (long long)l * PINS;
    if (vv.x & 1u) atomicMinFloat(rl + s.x, c0);
    if (vv.x & 2u) atomicMinFloat(rl + s.y, c0);
    if (vv.y & 1u) atomicMinFloat(rl + s.z, c1);
    if (vv.y & 2u) atomicMinFloat(rl + s.w, c1);
}

// ---------------- epilogue: slack for all levels ----------------
__global__ void sta_epilogue_kernel(const float* __restrict__ arr,
                                    const float* __restrict__ req,
                                    float* __restrict__ slack) {
    int t = blockIdx.x * blockDim.x + threadIdx.x;
    if (t >= LVL * PINS / 2) return;
    float2 r = ((const float2*)req)[t];
    float2 a = ((const float2*)arr)[t];
    ((float2*)slack)[t] = make_float2(r.x - a.x, r.y - a.y);
}

// ---------------------------------------------------------------------------
template <typename... Args>
static void launch_pdl(cudaStream_t st, dim3 grid, dim3 block, bool pdl,
                       void (*kern)(Args...), Args... args) {
    cudaLaunchConfig_t cfg = {};
    cfg.gridDim = grid;
    cfg.blockDim = block;
    cfg.stream = st;
    cudaLaunchAttribute at[1];
    if (pdl) {
        at[0].id = cudaLaunchAttributeProgrammaticStreamSerialization;
        at[0].val.programmaticStreamSerializationAllowed = 1;
        cfg.attrs = at;
        cfg.numAttrs = 1;
    }
    cudaLaunchKernelEx(&cfg, kern, args...);
}

extern "C" void kernel_launch(void* const* d_in, const int* in_sizes, int n_in,
                              void* d_out, int out_size) {
    const float*        delays = (const float*)d_in[0];
    const int2*         src    = (const int2*)d_in[1];
    const int2*         net    = (const int2*)d_in[2];
    const unsigned int* mask   = (const unsigned int*)d_in[3];

    float* out = (float*)d_out;
    const long long LP = (long long)LVL * PINS;

    float* arr      = out;           // [0,   LP)
    float* req      = out + LP;      // [LP,  2LP)
    float* slack    = out + 2 * LP;  // [2LP, 3LP)
    float* mask_out = out + 3 * LP;  // [3LP, 3LP+NNETS)
    long long mask_room = (long long)out_size - 3 * LP;

    cudaStream_t s0 = (cudaStream_t)0;

    cudaStream_t s2;
    cudaStreamCreateWithFlags(&s2, cudaStreamNonBlocking);
    cudaEvent_t evFork, evA, evJoin;
    cudaEventCreateWithFlags(&evFork, cudaEventDisableTiming);
    cudaEventCreateWithFlags(&evA,    cudaEventDisableTiming);
    cudaEventCreateWithFlags(&evJoin, cudaEventDisableTiming);

    // fork s2 from capture origin
    cudaEventRecord(evFork, s0);
    cudaStreamWaitEvent(s2, evFork, 0);

    // preA on s0 (valid bits + arr[0]); preB on s2 (req init + mask out)
    {
        int blocksA = ((LVL - 1) * PINS + 255) / 256;
        sta_preA_kernel<<<blocksA, 256, 0, s0>>>(delays, net, mask, arr);
        cudaEventRecord(evA, s0);

        int blocksB = (int)((LP + 255) / 256);
        sta_preB_kernel<<<blocksB, 256, 0, s2>>>(mask, req, mask_out, mask_room);
        cudaStreamWaitEvent(s2, evA, 0);   // bwd needs g_valid
    }

    const int T = 128;
    const int blocksP = (PINS + T - 1) / T;           // 1024
    const int blocksH = (PINS / 2 + T - 1) / T;       // 512

    // forward chain (s0): fused pairs (1,2)..(29,30), then level 31
    for (int l = 1; l + 1 < LVL; l += 2)
        launch_pdl(s0, dim3(blocksP), dim3(T), true,
                   sta_fwd2_kernel, delays, src, arr, l);
    launch_pdl(s0, dim3(blocksP), dim3(T), true,
               sta_fwd1_kernel, delays, src, arr, (int)(LVL - 1));

    // backward chain (s2)
    for (int l = LVL - 2; l >= 0; --l)
        launch_pdl(s2, dim3(blocksH), dim3(T), l != LVL - 2,
                   sta_bwd_kernel, delays, src, req, l);

    // join and compute slacks
    cudaEventRecord(evJoin, s2);
    cudaStreamWaitEvent(s0, evJoin, 0);
    {
        int blocksE = (int)((LP / 2 + 255) / 256);
        sta_epilogue_kernel<<<blocksE, 256, 0, s0>>>(arr, req, slack);
    }
}